// round 1
// baseline (speedup 1.0000x reference)
#include <cuda_runtime.h>
#include <math.h>

// Problem constants
#define BB   2
#define SS   2048
#define DD   512
#define HH   8
#define DKK  64
#define BHH  (BB*HH)

// ---------------- scratch (device globals; no allocation allowed) ----------
__device__ float g_qh[BHH*SS*DKK];          // [b][h][s][dk]  (8 MB)
__device__ float g_kh[BHH*SS*DKK];
__device__ float g_vh[BHH*SS*DKK];
__device__ float g_at[BB*SS*DD];            // attention out, [b][s][h*64+dk] (16 MB)
__device__ float g_cos[SS*DKK];             // RoPE tables (repeat-style freqs)
__device__ float g_sin[SS*DKK];
__device__ float g_sc[67108864];            // scores / probs, [bh][i][j] (256 MiB)

// ---------------- RoPE table ------------------------------------------------
__global__ void rope_tab_kernel()
{
    int idx = blockIdx.x * blockDim.x + threadIdx.x;   // (s, m), m = pair idx < 32
    if (idx >= SS * 32) return;
    int s = idx >> 5;
    int m = idx & 31;
    float f = (float)s * powf(10000.f, -(float)(2 * m) / 64.f);
    float sn, cs;
    sincosf(f, &sn, &cs);
    g_cos[s*64 + 2*m]     = cs;
    g_cos[s*64 + 2*m + 1] = cs;
    g_sin[s*64 + 2*m]     = sn;
    g_sin[s*64 + 2*m + 1] = sn;
}

// ---------------- fused QKV projection + RoPE -------------------------------
// y[t,d] = sum_c x[t,c] * W[d,c] + b[d]; grid.z selects q/k/v; RoPE on q,k.
// Tile 128x128, 256 threads, 8x8 microtile, K-tile 16.
__global__ __launch_bounds__(256) void proj_qkv_kernel(
    const float* __restrict__ qx, const float* __restrict__ kx, const float* __restrict__ vx,
    const float* __restrict__ Wq, const float* __restrict__ bq,
    const float* __restrict__ Wk, const float* __restrict__ bk,
    const float* __restrict__ Wv, const float* __restrict__ bv)
{
    __shared__ float As[128][17];
    __shared__ float Bs[128][17];

    int which = blockIdx.z;
    const float* X    = (which == 0) ? qx : (which == 1) ? kx : vx;
    const float* W    = (which == 0) ? Wq : (which == 1) ? Wk : Wv;
    const float* bias = (which == 0) ? bq : (which == 1) ? bk : bv;

    int tx = threadIdx.x, ty = threadIdx.y;
    int tid = ty * 16 + tx;
    int n0 = blockIdx.x * 128;
    int m0 = blockIdx.y * 128;

    float acc[8][8];
    #pragma unroll
    for (int i = 0; i < 8; i++)
        #pragma unroll
        for (int j = 0; j < 8; j++) acc[i][j] = 0.f;

    for (int k0 = 0; k0 < 512; k0 += 16) {
        #pragma unroll
        for (int u = 0; u < 2; u++) {
            int lin = tid + u * 256;          // 0..511 float4 slots (128 rows x 4)
            int row = lin >> 2;
            int c4  = (lin & 3) * 4;
            float4 av  = *(const float4*)(X + (size_t)(m0 + row) * 512 + k0 + c4);
            float4 wv4 = *(const float4*)(W + (size_t)(n0 + row) * 512 + k0 + c4);
            As[row][c4+0] = av.x;  As[row][c4+1] = av.y;
            As[row][c4+2] = av.z;  As[row][c4+3] = av.w;
            Bs[row][c4+0] = wv4.x; Bs[row][c4+1] = wv4.y;
            Bs[row][c4+2] = wv4.z; Bs[row][c4+3] = wv4.w;
        }
        __syncthreads();
        #pragma unroll
        for (int kk = 0; kk < 16; kk++) {
            float a[8], b[8];
            #pragma unroll
            for (int i = 0; i < 8; i++) a[i] = As[ty*8 + i][kk];       // broadcast
            #pragma unroll
            for (int j = 0; j < 8; j++) b[j] = Bs[tx + 16*j][kk];      // conflict-free
            #pragma unroll
            for (int i = 0; i < 8; i++)
                #pragma unroll
                for (int j = 0; j < 8; j++)
                    acc[i][j] = fmaf(a[i], b[j], acc[i][j]);
        }
        __syncthreads();
    }

    int rope = (which < 2);
    int cols[8];
    float bcol[8];
    #pragma unroll
    for (int j = 0; j < 8; j++) { cols[j] = n0 + tx + 16*j; bcol[j] = bias[cols[j]]; }

    float* Y = (which == 0) ? g_qh : (which == 1) ? g_kh : g_vh;

    #pragma unroll
    for (int i = 0; i < 8; i++) {
        int r    = m0 + ty*8 + i;
        int srow = r & (SS - 1);
        int bidx = r >> 11;
        float vals[8];
        #pragma unroll
        for (int j = 0; j < 8; j++) vals[j] = acc[i][j] + bcol[j];
        if (rope) {
            #pragma unroll
            for (int j = 0; j < 8; j++) {
                int dk = cols[j] & 63;
                float c  = g_cos[srow*64 + dk];
                float sn = g_sin[srow*64 + dk];
                float p  = __shfl_xor_sync(0xffffffffu, vals[j], 1);  // pair partner
                vals[j]  = (cols[j] & 1) ? fmaf(vals[j], c,  p * sn)
                                         : fmaf(vals[j], c, -p * sn);
            }
        }
        #pragma unroll
        for (int j = 0; j < 8; j++) {
            int d = cols[j];
            int h = d >> 6, dk = d & 63;
            Y[(((size_t)bidx*HH + h)*SS + srow)*DKK + dk] = vals[j];
        }
    }
}

// ---------------- output projection -----------------------------------------
__global__ __launch_bounds__(256) void out_proj_kernel(
    const float* __restrict__ W, const float* __restrict__ bias, float* __restrict__ out)
{
    __shared__ float As[128][17];
    __shared__ float Bs[128][17];

    int tx = threadIdx.x, ty = threadIdx.y;
    int tid = ty * 16 + tx;
    int n0 = blockIdx.x * 128;
    int m0 = blockIdx.y * 128;

    float acc[8][8];
    #pragma unroll
    for (int i = 0; i < 8; i++)
        #pragma unroll
        for (int j = 0; j < 8; j++) acc[i][j] = 0.f;

    for (int k0 = 0; k0 < 512; k0 += 16) {
        #pragma unroll
        for (int u = 0; u < 2; u++) {
            int lin = tid + u * 256;
            int row = lin >> 2;
            int c4  = (lin & 3) * 4;
            float4 av  = *(const float4*)(g_at + (size_t)(m0 + row) * 512 + k0 + c4);
            float4 wv4 = *(const float4*)(W    + (size_t)(n0 + row) * 512 + k0 + c4);
            As[row][c4+0] = av.x;  As[row][c4+1] = av.y;
            As[row][c4+2] = av.z;  As[row][c4+3] = av.w;
            Bs[row][c4+0] = wv4.x; Bs[row][c4+1] = wv4.y;
            Bs[row][c4+2] = wv4.z; Bs[row][c4+3] = wv4.w;
        }
        __syncthreads();
        #pragma unroll
        for (int kk = 0; kk < 16; kk++) {
            float a[8], b[8];
            #pragma unroll
            for (int i = 0; i < 8; i++) a[i] = As[ty*8 + i][kk];
            #pragma unroll
            for (int j = 0; j < 8; j++) b[j] = Bs[tx + 16*j][kk];
            #pragma unroll
            for (int i = 0; i < 8; i++)
                #pragma unroll
                for (int j = 0; j < 8; j++)
                    acc[i][j] = fmaf(a[i], b[j], acc[i][j]);
        }
        __syncthreads();
    }

    #pragma unroll
    for (int i = 0; i < 8; i++) {
        int r = m0 + ty*8 + i;
        #pragma unroll
        for (int j = 0; j < 8; j++) {
            int d = n0 + tx + 16*j;
            out[(size_t)r*512 + d] = acc[i][j] + bias[d];
        }
    }
}

// ---------------- causal score GEMM: S = (Q K^T) / 8 ------------------------
// Per (b,h): 2048x2048, only lower block-triangular 128x128 tiles.
__global__ __launch_bounds__(256) void score_kernel()
{
    int qt = blockIdx.x, kt = blockIdx.y, bh = blockIdx.z;
    if (kt > qt) return;

    __shared__ float Qs[128][33];
    __shared__ float Ks[128][33];

    const float* qb = g_qh + (size_t)bh * SS * DKK;
    const float* kb = g_kh + (size_t)bh * SS * DKK;

    int tid = threadIdx.x;
    int tx = tid & 15, ty = tid >> 4;
    int i0 = qt * 128, j0 = kt * 128;

    float acc[8][8];
    #pragma unroll
    for (int i = 0; i < 8; i++)
        #pragma unroll
        for (int j = 0; j < 8; j++) acc[i][j] = 0.f;

    for (int k0 = 0; k0 < 64; k0 += 32) {
        #pragma unroll
        for (int u = 0; u < 4; u++) {
            int lin = tid + u * 256;           // 0..1023 (128 rows x 8 float4)
            int row = lin >> 3;
            int c4  = (lin & 7) * 4;
            float4 qv = *(const float4*)(qb + (size_t)(i0 + row) * 64 + k0 + c4);
            float4 kv = *(const float4*)(kb + (size_t)(j0 + row) * 64 + k0 + c4);
            Qs[row][c4+0] = qv.x; Qs[row][c4+1] = qv.y;
            Qs[row][c4+2] = qv.z; Qs[row][c4+3] = qv.w;
            Ks[row][c4+0] = kv.x; Ks[row][c4+1] = kv.y;
            Ks[row][c4+2] = kv.z; Ks[row][c4+3] = kv.w;
        }
        __syncthreads();
        #pragma unroll
        for (int kk = 0; kk < 32; kk++) {
            float a[8], b[8];
            #pragma unroll
            for (int i = 0; i < 8; i++) a[i] = Qs[ty*8 + i][kk];
            #pragma unroll
            for (int j = 0; j < 8; j++) b[j] = Ks[tx + 16*j][kk];
            #pragma unroll
            for (int i = 0; i < 8; i++)
                #pragma unroll
                for (int j = 0; j < 8; j++)
                    acc[i][j] = fmaf(a[i], b[j], acc[i][j]);
        }
        __syncthreads();
    }

    float* C = g_sc + (size_t)bh * SS * SS;
    #pragma unroll
    for (int i = 0; i < 8; i++) {
        int gi = i0 + ty*8 + i;
        #pragma unroll
        for (int j = 0; j < 8; j++)
            C[(size_t)gi * SS + j0 + tx + 16*j] = acc[i][j] * 0.125f;
    }
}

// ---------------- per-row decay + double softmax -----------------------------
// One CTA (256 thr) per (b,h,i). Each thread owns 8 contiguous columns.
__device__ __forceinline__ float block_max(float v, float* sm)
{
    int tid = threadIdx.x;
    sm[tid] = v; __syncthreads();
    for (int s = 128; s > 0; s >>= 1) {
        if (tid < s) sm[tid] = fmaxf(sm[tid], sm[tid + s]);
        __syncthreads();
    }
    float r = sm[0]; __syncthreads();
    return r;
}
__device__ __forceinline__ float block_sum(float v, float* sm)
{
    int tid = threadIdx.x;
    sm[tid] = v; __syncthreads();
    for (int s = 128; s > 0; s >>= 1) {
        if (tid < s) sm[tid] += sm[tid + s];
        __syncthreads();
    }
    float r = sm[0]; __syncthreads();
    return r;
}

__global__ __launch_bounds__(256) void row_kernel(const float* __restrict__ gammas)
{
    __shared__ float sm[256];
    int rid = blockIdx.x;                 // bh * S + i
    int bh  = rid >> 11;
    int i   = rid & (SS - 1);
    int h   = bh & (HH - 1);
    int tid = threadIdx.x;

    float* row = g_sc + (size_t)bh * SS * SS + (size_t)i * SS;
    int lim = ((i >> 7) + 1) << 7;        // zero-fill to 128-aligned PV k-extent

    if (i == 0) {                          // shift_down zeroes query row 0
        for (int j = tid; j < 128; j += 256) row[j] = 0.f;
        return;
    }

    const int base = tid * 8;
    float sv[8];
    #pragma unroll
    for (int u = 0; u < 8; u++) {
        int j = base + u;
        sv[u] = (j <= i) ? row[j] : -3.0e38f;
    }

    // --- softmax 1: max ---
    float mloc = sv[0];
    #pragma unroll
    for (int u = 1; u < 8; u++) mloc = fmaxf(mloc, sv[u]);
    float m1 = block_max(mloc, sm);

    // --- exp + thread-local inclusive prefix ---
    float epre[8];
    float run = 0.f;
    #pragma unroll
    for (int u = 0; u < 8; u++) {
        float ev = (base + u <= i) ? __expf(sv[u] - m1) : 0.f;
        run += ev;
        epre[u] = run;
    }

    // --- block inclusive scan over per-thread sums ---
    sm[tid] = run; __syncthreads();
    for (int d = 1; d < 256; d <<= 1) {
        float t = (tid >= d) ? sm[tid - d] : 0.f;
        __syncthreads();
        sm[tid] += t;
        __syncthreads();
    }
    float incl = sm[tid];
    float l1   = sm[255];
    __syncthreads();
    float off = incl - run;

    // --- decay + rescoring ---
    float gam = gammas[h * SS + i];
    float sp  = (gam > 20.f) ? gam : log1pf(__expf(gam));
    float g   = -sp;
    float inv_l1 = 1.f / l1;

    float tv[8];
    float m2loc = -3.0e38f;
    #pragma unroll
    for (int u = 0; u < 8; u++) {
        int j = base + u;
        if (j <= i) {
            float suffix = l1 - (off + epre[u]);              // sum of exp beyond j
            float dsq    = suffix * inv_l1 * (float)(i - j);  // (1-distcum)*|i-j|
            float dist   = sqrtf(fmaxf(dsq, 0.f));
            float eff    = fmaxf(__expf(dist * g), 1e-5f);    // clip; upper 1e5 unreachable
            tv[u] = eff * sv[u];
            m2loc = fmaxf(m2loc, tv[u]);
        } else {
            tv[u] = -3.0e38f;
        }
    }

    // --- softmax 2 ---
    float m2 = block_max(m2loc, sm);
    float e2[8];
    float lsum = 0.f;
    #pragma unroll
    for (int u = 0; u < 8; u++) {
        e2[u] = (base + u <= i) ? __expf(tv[u] - m2) : 0.f;
        lsum += e2[u];
    }
    float l2 = block_sum(lsum, sm);
    float inv = 1.f / l2;

    #pragma unroll
    for (int u = 0; u < 8; u++) {
        int j = base + u;
        if (j < lim) row[j] = (j <= i) ? e2[u] * inv : 0.f;
    }
}

// ---------------- causal PV GEMM: O = P @ V ----------------------------------
// Per (b,h): out (2048x64) = P(2048x2048, lower) @ V(2048x64). 128-row tiles,
// k runs over [0, (qt+1)*128). Writes to g_at in [b][s][h*64+dk] layout.
__global__ __launch_bounds__(256) void pv_kernel()
{
    int qt = blockIdx.x, bh = blockIdx.z;
    __shared__ float Ps[128][33];
    __shared__ float Vs[32][65];

    const float* P  = g_sc + (size_t)bh * SS * SS;
    const float* vb = g_vh + (size_t)bh * SS * DKK;

    int tid = threadIdx.x;
    int tx = tid & 15, ty = tid >> 4;
    int m0 = qt * 128;

    float acc[8][4];
    #pragma unroll
    for (int i = 0; i < 8; i++)
        #pragma unroll
        for (int j = 0; j < 4; j++) acc[i][j] = 0.f;

    int kmax = (qt + 1) * 128;
    for (int k0 = 0; k0 < kmax; k0 += 32) {
        #pragma unroll
        for (int u = 0; u < 4; u++) {
            int lin = tid + u * 256;            // Ps: 128x32 = 1024 float4
            int row = lin >> 3;
            int c4  = (lin & 7) * 4;
            float4 pv4 = *(const float4*)(P + (size_t)(m0 + row) * SS + k0 + c4);
            Ps[row][c4+0] = pv4.x; Ps[row][c4+1] = pv4.y;
            Ps[row][c4+2] = pv4.z; Ps[row][c4+3] = pv4.w;
        }
        #pragma unroll
        for (int u = 0; u < 2; u++) {
            int lin = tid + u * 256;            // Vs: 32x64 = 512 float4
            int row = lin >> 4;
            int c4  = (lin & 15) * 4;
            float4 vv = *(const float4*)(vb + (size_t)(k0 + row) * 64 + c4);
            Vs[row][c4+0] = vv.x; Vs[row][c4+1] = vv.y;
            Vs[row][c4+2] = vv.z; Vs[row][c4+3] = vv.w;
        }
        __syncthreads();
        #pragma unroll
        for (int kk = 0; kk < 32; kk++) {
            float a[8], b[4];
            #pragma unroll
            for (int i = 0; i < 8; i++) a[i] = Ps[ty*8 + i][kk];
            #pragma unroll
            for (int j = 0; j < 4; j++) b[j] = Vs[kk][tx + 16*j];
            #pragma unroll
            for (int i = 0; i < 8; i++)
                #pragma unroll
                for (int j = 0; j < 4; j++)
                    acc[i][j] = fmaf(a[i], b[j], acc[i][j]);
        }
        __syncthreads();
    }

    int b = bh >> 3, h = bh & 7;
    #pragma unroll
    for (int i = 0; i < 8; i++) {
        int s = m0 + ty*8 + i;
        #pragma unroll
        for (int j = 0; j < 4; j++)
            g_at[((size_t)b * SS + s) * DD + h*64 + tx + 16*j] = acc[i][j];
    }
}

// ---------------- launcher ----------------------------------------------------
extern "C" void kernel_launch(void* const* d_in, const int* in_sizes, int n_in,
                              void* d_out, int out_size)
{
    const float* q      = (const float*)d_in[0];
    const float* k      = (const float*)d_in[1];
    const float* v      = (const float*)d_in[2];
    // d_in[3] = ltime (unused), d_in[4] = mask (causal by construction; unused)
    const float* Wq     = (const float*)d_in[5];
    const float* bq     = (const float*)d_in[6];
    const float* Wk     = (const float*)d_in[7];
    const float* bk     = (const float*)d_in[8];
    const float* Wv     = (const float*)d_in[9];
    const float* bv     = (const float*)d_in[10];
    const float* Wo     = (const float*)d_in[11];
    const float* bo     = (const float*)d_in[12];
    const float* gammas = (const float*)d_in[13];
    float* out = (float*)d_out;

    dim3 pt(16, 16);

    rope_tab_kernel<<<(SS * 32 + 255) / 256, 256>>>();
    proj_qkv_kernel<<<dim3(4, 32, 3), pt>>>(q, k, v, Wq, bq, Wk, bk, Wv, bv);
    score_kernel<<<dim3(16, 16, 16), 256>>>();
    row_kernel<<<BHH * SS, 256>>>(gammas);
    pv_kernel<<<dim3(16, 1, 16), 256>>>();
    out_proj_kernel<<<dim3(4, 32), pt>>>(Wo, bo, out);
}

// round 2
// speedup vs baseline: 1.8647x; 1.8647x over previous
#include <cuda_runtime.h>
#include <math.h>
#include <stdint.h>

#define BB   2
#define SS   2048
#define DD   512
#define HH   8
#define DKK  64
#define BHH  (BB*HH)

// ---------------- scratch (device globals; no allocation allowed) ----------
__device__ float g_qh[BHH*SS*DKK];          // [bh][s][dk]   8 MB
__device__ float g_kh[BHH*SS*DKK];
__device__ float g_vt[BHH*DKK*SS];          // transposed V: [bh][dk][s]
__device__ float g_at[BB*SS*DD];            // attention out [b][s][h*64+dk]
__device__ float g_cos[SS*DKK];
__device__ float g_sin[SS*DKK];
__device__ float g_sc[67108864];            // scores/probs [bh][i][j] 256 MiB

// ---------------- helpers ----------------------------------------------------
__device__ __forceinline__ uint32_t f2tf(float f)
{
    uint32_t u;
    asm("cvt.rna.tf32.f32 %0, %1;" : "=r"(u) : "f"(f));
    return u;
}

__device__ __forceinline__ void mma8(float* c, const uint32_t* a, const uint32_t* b)
{
    asm volatile(
        "mma.sync.aligned.m16n8k8.row.col.f32.tf32.tf32.f32 "
        "{%0,%1,%2,%3}, {%4,%5,%6,%7}, {%8,%9}, {%0,%1,%2,%3};\n"
        : "+f"(c[0]), "+f"(c[1]), "+f"(c[2]), "+f"(c[3])
        : "r"(a[0]), "r"(a[1]), "r"(a[2]), "r"(a[3]), "r"(b[0]), "r"(b[1]));
}

// ---------------- RoPE table ------------------------------------------------
__global__ void rope_tab_kernel()
{
    int idx = blockIdx.x * blockDim.x + threadIdx.x;
    if (idx >= SS * 32) return;
    int s = idx >> 5;
    int m = idx & 31;
    float f = (float)s * powf(10000.f, -(float)(2 * m) / 64.f);
    float sn, cs;
    sincosf(f, &sn, &cs);
    g_cos[s*64 + 2*m]     = cs;
    g_cos[s*64 + 2*m + 1] = cs;
    g_sin[s*64 + 2*m]     = sn;
    g_sin[s*64 + 2*m + 1] = sn;
}

// ---------------- fused QKV projection + RoPE (tf32 mma) ---------------------
// y[t,d] = sum_c X[t,c] * W[d,c] + b[d].  Tile 128x128, 8 warps (2m x 4n),
// warp tile 64x32, m16n8k8 frags.  RoPE applied in-register (c0/c1 are an
// adjacent even/odd column pair).  V written transposed to g_vt.
__global__ __launch_bounds__(256) void proj_kernel(
    const float* __restrict__ qx, const float* __restrict__ kx, const float* __restrict__ vx,
    const float* __restrict__ Wq, const float* __restrict__ bq,
    const float* __restrict__ Wk, const float* __restrict__ bk,
    const float* __restrict__ Wv, const float* __restrict__ bv)
{
    __shared__ uint32_t As[128][36];
    __shared__ uint32_t Bs[128][36];

    int which = blockIdx.z;
    const float* X    = (which == 0) ? qx : (which == 1) ? kx : vx;
    const float* W    = (which == 0) ? Wq : (which == 1) ? Wk : Wv;
    const float* bias = (which == 0) ? bq : (which == 1) ? bk : bv;

    int tid  = threadIdx.x;
    int wid  = tid >> 5, lane = tid & 31;
    int g    = lane >> 2, t = lane & 3;
    int wm   = wid >> 2, wn = wid & 3;
    int n0   = blockIdx.x * 128;
    int m0   = blockIdx.y * 128;

    float c[4][4][4];
    #pragma unroll
    for (int mf = 0; mf < 4; mf++)
        #pragma unroll
        for (int nf = 0; nf < 4; nf++)
            #pragma unroll
            for (int u = 0; u < 4; u++) c[mf][nf][u] = 0.f;

    int lr = tid >> 1;
    int lc = (tid & 1) * 16;

    for (int k0 = 0; k0 < 512; k0 += 32) {
        #pragma unroll
        for (int u = 0; u < 4; u++) {
            float4 xa = *(const float4*)(X + (size_t)(m0 + lr) * 512 + k0 + lc + u*4);
            float4 wb = *(const float4*)(W + (size_t)(n0 + lr) * 512 + k0 + lc + u*4);
            As[lr][lc+u*4+0] = f2tf(xa.x); As[lr][lc+u*4+1] = f2tf(xa.y);
            As[lr][lc+u*4+2] = f2tf(xa.z); As[lr][lc+u*4+3] = f2tf(xa.w);
            Bs[lr][lc+u*4+0] = f2tf(wb.x); Bs[lr][lc+u*4+1] = f2tf(wb.y);
            Bs[lr][lc+u*4+2] = f2tf(wb.z); Bs[lr][lc+u*4+3] = f2tf(wb.w);
        }
        __syncthreads();
        #pragma unroll
        for (int k8 = 0; k8 < 32; k8 += 8) {
            uint32_t a[4][4], b[4][2];
            #pragma unroll
            for (int mf = 0; mf < 4; mf++) {
                int r = wm*64 + mf*16 + g;
                a[mf][0] = As[r][k8+t];     a[mf][1] = As[r+8][k8+t];
                a[mf][2] = As[r][k8+t+4];   a[mf][3] = As[r+8][k8+t+4];
            }
            #pragma unroll
            for (int nf = 0; nf < 4; nf++) {
                int rn = wn*32 + nf*8 + g;
                b[nf][0] = Bs[rn][k8+t];    b[nf][1] = Bs[rn][k8+t+4];
            }
            #pragma unroll
            for (int mf = 0; mf < 4; mf++)
                #pragma unroll
                for (int nf = 0; nf < 4; nf++)
                    mma8(c[mf][nf], a[mf], b[nf]);
        }
        __syncthreads();
    }

    // ---- epilogue: bias (+ RoPE for q/k), scatter ----
    #pragma unroll
    for (int nf = 0; nf < 4; nf++) {
        int col = n0 + wn*32 + nf*8 + t*2;      // even column
        int hh  = col >> 6, dk = col & 63;
        float bce = bias[col], bco = bias[col+1];
        #pragma unroll
        for (int mf = 0; mf < 4; mf++) {
            #pragma unroll
            for (int half = 0; half < 2; half++) {
                int row  = m0 + wm*64 + mf*16 + g + half*8;
                int srow = row & (SS-1);
                int bidx = row >> 11;
                float e = c[mf][nf][half*2+0] + bce;
                float o = c[mf][nf][half*2+1] + bco;
                if (which < 2) {
                    float cs = g_cos[srow*64 + dk];
                    float sn = g_sin[srow*64 + dk];
                    float ne = e*cs - o*sn;
                    float no = o*cs + e*sn;
                    float* Y = (which == 0) ? g_qh : g_kh;
                    *(float2*)(Y + (((size_t)(bidx*HH + hh))*SS + srow)*DKK + dk)
                        = make_float2(ne, no);
                } else {
                    size_t vb = (size_t)(bidx*HH + hh) * DKK;
                    g_vt[(vb + dk    )*SS + srow] = e;
                    g_vt[(vb + dk + 1)*SS + srow] = o;
                }
            }
        }
    }
}

// ---------------- output projection (tf32 mma) --------------------------------
__global__ __launch_bounds__(256) void out_proj_kernel(
    const float* __restrict__ W, const float* __restrict__ bias, float* __restrict__ out)
{
    __shared__ uint32_t As[128][36];
    __shared__ uint32_t Bs[128][36];

    int tid  = threadIdx.x;
    int wid  = tid >> 5, lane = tid & 31;
    int g    = lane >> 2, t = lane & 3;
    int wm   = wid >> 2, wn = wid & 3;
    int n0   = blockIdx.x * 128;
    int m0   = blockIdx.y * 128;

    float c[4][4][4];
    #pragma unroll
    for (int mf = 0; mf < 4; mf++)
        #pragma unroll
        for (int nf = 0; nf < 4; nf++)
            #pragma unroll
            for (int u = 0; u < 4; u++) c[mf][nf][u] = 0.f;

    int lr = tid >> 1;
    int lc = (tid & 1) * 16;

    for (int k0 = 0; k0 < 512; k0 += 32) {
        #pragma unroll
        for (int u = 0; u < 4; u++) {
            float4 xa = *(const float4*)(g_at + (size_t)(m0 + lr) * 512 + k0 + lc + u*4);
            float4 wb = *(const float4*)(W    + (size_t)(n0 + lr) * 512 + k0 + lc + u*4);
            As[lr][lc+u*4+0] = f2tf(xa.x); As[lr][lc+u*4+1] = f2tf(xa.y);
            As[lr][lc+u*4+2] = f2tf(xa.z); As[lr][lc+u*4+3] = f2tf(xa.w);
            Bs[lr][lc+u*4+0] = f2tf(wb.x); Bs[lr][lc+u*4+1] = f2tf(wb.y);
            Bs[lr][lc+u*4+2] = f2tf(wb.z); Bs[lr][lc+u*4+3] = f2tf(wb.w);
        }
        __syncthreads();
        #pragma unroll
        for (int k8 = 0; k8 < 32; k8 += 8) {
            uint32_t a[4][4], b[4][2];
            #pragma unroll
            for (int mf = 0; mf < 4; mf++) {
                int r = wm*64 + mf*16 + g;
                a[mf][0] = As[r][k8+t];     a[mf][1] = As[r+8][k8+t];
                a[mf][2] = As[r][k8+t+4];   a[mf][3] = As[r+8][k8+t+4];
            }
            #pragma unroll
            for (int nf = 0; nf < 4; nf++) {
                int rn = wn*32 + nf*8 + g;
                b[nf][0] = Bs[rn][k8+t];    b[nf][1] = Bs[rn][k8+t+4];
            }
            #pragma unroll
            for (int mf = 0; mf < 4; mf++)
                #pragma unroll
                for (int nf = 0; nf < 4; nf++)
                    mma8(c[mf][nf], a[mf], b[nf]);
        }
        __syncthreads();
    }

    #pragma unroll
    for (int nf = 0; nf < 4; nf++) {
        int col = n0 + wn*32 + nf*8 + t*2;
        float bce = bias[col], bco = bias[col+1];
        #pragma unroll
        for (int mf = 0; mf < 4; mf++) {
            #pragma unroll
            for (int half = 0; half < 2; half++) {
                int row = m0 + wm*64 + mf*16 + g + half*8;
                *(float2*)(out + (size_t)row*512 + col)
                    = make_float2(c[mf][nf][half*2+0] + bce, c[mf][nf][half*2+1] + bco);
            }
        }
    }
}

// ---------------- causal score GEMM S = (Q K^T)/8 (tf32 mma) ------------------
__global__ __launch_bounds__(256) void score_kernel()
{
    int qt = blockIdx.x, kt = blockIdx.y, bh = blockIdx.z;
    if (kt > qt) return;

    __shared__ uint32_t Qs[128][36];
    __shared__ uint32_t Ks[128][36];

    const float* qb = g_qh + (size_t)bh * SS * DKK;
    const float* kb = g_kh + (size_t)bh * SS * DKK;

    int tid  = threadIdx.x;
    int wid  = tid >> 5, lane = tid & 31;
    int g    = lane >> 2, t = lane & 3;
    int wm   = wid >> 2, wn = wid & 3;
    int i0   = qt * 128, j0 = kt * 128;

    float c[4][4][4];
    #pragma unroll
    for (int mf = 0; mf < 4; mf++)
        #pragma unroll
        for (int nf = 0; nf < 4; nf++)
            #pragma unroll
            for (int u = 0; u < 4; u++) c[mf][nf][u] = 0.f;

    int lr = tid >> 1;
    int lc = (tid & 1) * 16;

    #pragma unroll
    for (int k0 = 0; k0 < 64; k0 += 32) {
        #pragma unroll
        for (int u = 0; u < 4; u++) {
            float4 qv = *(const float4*)(qb + (size_t)(i0 + lr) * 64 + k0 + lc + u*4);
            float4 kv = *(const float4*)(kb + (size_t)(j0 + lr) * 64 + k0 + lc + u*4);
            Qs[lr][lc+u*4+0] = f2tf(qv.x); Qs[lr][lc+u*4+1] = f2tf(qv.y);
            Qs[lr][lc+u*4+2] = f2tf(qv.z); Qs[lr][lc+u*4+3] = f2tf(qv.w);
            Ks[lr][lc+u*4+0] = f2tf(kv.x); Ks[lr][lc+u*4+1] = f2tf(kv.y);
            Ks[lr][lc+u*4+2] = f2tf(kv.z); Ks[lr][lc+u*4+3] = f2tf(kv.w);
        }
        __syncthreads();
        #pragma unroll
        for (int k8 = 0; k8 < 32; k8 += 8) {
            uint32_t a[4][4], b[4][2];
            #pragma unroll
            for (int mf = 0; mf < 4; mf++) {
                int r = wm*64 + mf*16 + g;
                a[mf][0] = Qs[r][k8+t];     a[mf][1] = Qs[r+8][k8+t];
                a[mf][2] = Qs[r][k8+t+4];   a[mf][3] = Qs[r+8][k8+t+4];
            }
            #pragma unroll
            for (int nf = 0; nf < 4; nf++) {
                int rn = wn*32 + nf*8 + g;
                b[nf][0] = Ks[rn][k8+t];    b[nf][1] = Ks[rn][k8+t+4];
            }
            #pragma unroll
            for (int mf = 0; mf < 4; mf++)
                #pragma unroll
                for (int nf = 0; nf < 4; nf++)
                    mma8(c[mf][nf], a[mf], b[nf]);
        }
        __syncthreads();
    }

    float* C = g_sc + (size_t)bh * SS * SS;
    #pragma unroll
    for (int nf = 0; nf < 4; nf++) {
        int col = j0 + wn*32 + nf*8 + t*2;
        #pragma unroll
        for (int mf = 0; mf < 4; mf++) {
            #pragma unroll
            for (int half = 0; half < 2; half++) {
                int row = i0 + wm*64 + mf*16 + g + half*8;
                *(float2*)(C + (size_t)row*SS + col)
                    = make_float2(c[mf][nf][half*2+0] * 0.125f,
                                  c[mf][nf][half*2+1] * 0.125f);
            }
        }
    }
}

// ---------------- per-row decay + double softmax (warp-shuffle version) -------
__global__ __launch_bounds__(256) void row_kernel(const float* __restrict__ gammas)
{
    __shared__ float swp[40];
    int rid = blockIdx.x;
    int bh  = rid >> 11;
    int i   = rid & (SS - 1);
    int h   = bh & (HH - 1);
    int tid = threadIdx.x, wid = tid >> 5, lane = tid & 31;

    float* row = g_sc + (size_t)bh * SS * SS + (size_t)i * SS;
    int lim = ((i >> 7) + 1) << 7;

    if (i == 0) {
        if (tid < 32) ((float4*)row)[tid] = make_float4(0.f, 0.f, 0.f, 0.f);
        return;
    }

    const int base = tid * 8;
    float sv[8];
    if (base <= i) {
        float4 v0 = *(const float4*)(row + base);
        float4 v1 = *(const float4*)(row + base + 4);
        sv[0]=v0.x; sv[1]=v0.y; sv[2]=v0.z; sv[3]=v0.w;
        sv[4]=v1.x; sv[5]=v1.y; sv[6]=v1.z; sv[7]=v1.w;
    } else {
        #pragma unroll
        for (int u = 0; u < 8; u++) sv[u] = 0.f;
    }

    // --- softmax 1: max ---
    float mloc = -3.0e38f;
    #pragma unroll
    for (int u = 0; u < 8; u++)
        if (base + u <= i) mloc = fmaxf(mloc, sv[u]);
    #pragma unroll
    for (int o = 16; o > 0; o >>= 1)
        mloc = fmaxf(mloc, __shfl_xor_sync(0xffffffffu, mloc, o));
    if (lane == 0) swp[wid] = mloc;
    __syncthreads();
    if (tid == 0) {
        float m = swp[0];
        #pragma unroll
        for (int w = 1; w < 8; w++) m = fmaxf(m, swp[w]);
        swp[8] = m;
    }
    __syncthreads();
    float m1 = swp[8];

    // --- exp + thread-local inclusive prefix ---
    float epre[8];
    float run = 0.f;
    #pragma unroll
    for (int u = 0; u < 8; u++) {
        float ev = (base + u <= i) ? __expf(sv[u] - m1) : 0.f;
        run += ev;
        epre[u] = run;
    }

    // --- warp inclusive scan + cross-warp combine ---
    float x = run;
    #pragma unroll
    for (int d = 1; d < 32; d <<= 1) {
        float y = __shfl_up_sync(0xffffffffu, x, d);
        if (lane >= d) x += y;
    }
    if (lane == 31) swp[16 + wid] = x;
    __syncthreads();
    if (tid == 0) {
        float s = 0.f;
        #pragma unroll
        for (int w = 0; w < 8; w++) { float tv = swp[16 + w]; swp[24 + w] = s; s += tv; }
        swp[32] = s;
    }
    __syncthreads();
    float off = swp[24 + wid] + (x - run);   // exclusive prefix for this thread
    float l1  = swp[32];

    // --- decay + rescoring ---
    float gam = gammas[h * SS + i];
    float sp  = (gam > 20.f) ? gam : log1pf(__expf(gam));
    float gg  = -sp;
    float inv_l1 = 1.f / l1;

    float tv[8];
    float m2loc = -3.0e38f;
    #pragma unroll
    for (int u = 0; u < 8; u++) {
        int j = base + u;
        if (j <= i) {
            float suffix = l1 - (off + epre[u]);
            float dsq    = suffix * inv_l1 * (float)(i - j);
            float dist   = sqrtf(fmaxf(dsq, 0.f));
            float eff    = fmaxf(__expf(dist * gg), 1e-5f);
            tv[u] = eff * sv[u];
            m2loc = fmaxf(m2loc, tv[u]);
        } else {
            tv[u] = -3.0e38f;
        }
    }

    // --- softmax 2: max ---
    #pragma unroll
    for (int o = 16; o > 0; o >>= 1)
        m2loc = fmaxf(m2loc, __shfl_xor_sync(0xffffffffu, m2loc, o));
    if (lane == 0) swp[wid] = m2loc;
    __syncthreads();
    if (tid == 0) {
        float m = swp[0];
        #pragma unroll
        for (int w = 1; w < 8; w++) m = fmaxf(m, swp[w]);
        swp[9] = m;
    }
    __syncthreads();
    float m2 = swp[9];

    float e2[8];
    float lsum = 0.f;
    #pragma unroll
    for (int u = 0; u < 8; u++) {
        e2[u] = (base + u <= i) ? __expf(tv[u] - m2) : 0.f;
        lsum += e2[u];
    }
    #pragma unroll
    for (int o = 16; o > 0; o >>= 1)
        lsum += __shfl_xor_sync(0xffffffffu, lsum, o);
    if (lane == 0) swp[16 + wid] = lsum;
    __syncthreads();
    if (tid == 0) {
        float s = 0.f;
        #pragma unroll
        for (int w = 0; w < 8; w++) s += swp[16 + w];
        swp[10] = s;
    }
    __syncthreads();
    float inv = 1.f / swp[10];

    if (base < lim) {
        float o0 = (base + 0 <= i) ? e2[0]*inv : 0.f;
        float o1 = (base + 1 <= i) ? e2[1]*inv : 0.f;
        float o2 = (base + 2 <= i) ? e2[2]*inv : 0.f;
        float o3 = (base + 3 <= i) ? e2[3]*inv : 0.f;
        float o4 = (base + 4 <= i) ? e2[4]*inv : 0.f;
        float o5 = (base + 5 <= i) ? e2[5]*inv : 0.f;
        float o6 = (base + 6 <= i) ? e2[6]*inv : 0.f;
        float o7 = (base + 7 <= i) ? e2[7]*inv : 0.f;
        *(float4*)(row + base)     = make_float4(o0, o1, o2, o3);
        *(float4*)(row + base + 4) = make_float4(o4, o5, o6, o7);
    }
}

// ---------------- causal PV GEMM O = P @ V (tf32 mma) --------------------------
// A = P [i][j] (k=j contiguous), B = V^T [dk][j] (k=j contiguous).
// 8 warps (4m x 2n), warp tile 32x32.
__global__ __launch_bounds__(256) void pv_kernel()
{
    int qt = blockIdx.x, bh = blockIdx.y;

    __shared__ uint32_t Ps[128][36];
    __shared__ uint32_t Vs[64][36];

    const float* P  = g_sc + (size_t)bh * SS * SS;
    const float* vb = g_vt + (size_t)bh * DKK * SS;

    int tid  = threadIdx.x;
    int wid  = tid >> 5, lane = tid & 31;
    int g    = lane >> 2, t = lane & 3;
    int wm   = wid >> 1, wn = wid & 1;
    int m0   = qt * 128;

    float c[2][4][4];
    #pragma unroll
    for (int mf = 0; mf < 2; mf++)
        #pragma unroll
        for (int nf = 0; nf < 4; nf++)
            #pragma unroll
            for (int u = 0; u < 4; u++) c[mf][nf][u] = 0.f;

    int lr = tid >> 1;
    int lc = (tid & 1) * 16;
    int kmax = (qt + 1) * 128;

    for (int k0 = 0; k0 < kmax; k0 += 32) {
        #pragma unroll
        for (int u = 0; u < 4; u++) {
            float4 pv = *(const float4*)(P + (size_t)(m0 + lr) * SS + k0 + lc + u*4);
            Ps[lr][lc+u*4+0] = f2tf(pv.x); Ps[lr][lc+u*4+1] = f2tf(pv.y);
            Ps[lr][lc+u*4+2] = f2tf(pv.z); Ps[lr][lc+u*4+3] = f2tf(pv.w);
        }
        #pragma unroll
        for (int u = 0; u < 2; u++) {
            int lin = tid + u * 256;          // 512 float4 slots (64 rows x 8)
            int rowv = lin >> 3;
            int c4   = (lin & 7) * 4;
            float4 vv = *(const float4*)(vb + (size_t)rowv * SS + k0 + c4);
            Vs[rowv][c4+0] = f2tf(vv.x); Vs[rowv][c4+1] = f2tf(vv.y);
            Vs[rowv][c4+2] = f2tf(vv.z); Vs[rowv][c4+3] = f2tf(vv.w);
        }
        __syncthreads();
        #pragma unroll
        for (int k8 = 0; k8 < 32; k8 += 8) {
            uint32_t a[2][4], b[4][2];
            #pragma unroll
            for (int mf = 0; mf < 2; mf++) {
                int r = wm*32 + mf*16 + g;
                a[mf][0] = Ps[r][k8+t];     a[mf][1] = Ps[r+8][k8+t];
                a[mf][2] = Ps[r][k8+t+4];   a[mf][3] = Ps[r+8][k8+t+4];
            }
            #pragma unroll
            for (int nf = 0; nf < 4; nf++) {
                int rn = wn*32 + nf*8 + g;
                b[nf][0] = Vs[rn][k8+t];    b[nf][1] = Vs[rn][k8+t+4];
            }
            #pragma unroll
            for (int mf = 0; mf < 2; mf++)
                #pragma unroll
                for (int nf = 0; nf < 4; nf++)
                    mma8(c[mf][nf], a[mf], b[nf]);
        }
        __syncthreads();
    }

    int b = bh >> 3, h = bh & 7;
    #pragma unroll
    for (int nf = 0; nf < 4; nf++) {
        int dk = wn*32 + nf*8 + t*2;
        #pragma unroll
        for (int mf = 0; mf < 2; mf++) {
            #pragma unroll
            for (int half = 0; half < 2; half++) {
                int s = m0 + wm*32 + mf*16 + g + half*8;
                *(float2*)(g_at + ((size_t)b * SS + s) * DD + h*64 + dk)
                    = make_float2(c[mf][nf][half*2+0], c[mf][nf][half*2+1]);
            }
        }
    }
}

// ---------------- launcher ----------------------------------------------------
extern "C" void kernel_launch(void* const* d_in, const int* in_sizes, int n_in,
                              void* d_out, int out_size)
{
    const float* q      = (const float*)d_in[0];
    const float* k      = (const float*)d_in[1];
    const float* v      = (const float*)d_in[2];
    const float* Wq     = (const float*)d_in[5];
    const float* bq     = (const float*)d_in[6];
    const float* Wk     = (const float*)d_in[7];
    const float* bk     = (const float*)d_in[8];
    const float* Wv     = (const float*)d_in[9];
    const float* bv     = (const float*)d_in[10];
    const float* Wo     = (const float*)d_in[11];
    const float* bo     = (const float*)d_in[12];
    const float* gammas = (const float*)d_in[13];
    float* out = (float*)d_out;

    rope_tab_kernel<<<(SS * 32 + 255) / 256, 256>>>();
    proj_kernel<<<dim3(4, 32, 3), 256>>>(q, k, v, Wq, bq, Wk, bk, Wv, bv);
    score_kernel<<<dim3(16, 16, 16), 256>>>();
    row_kernel<<<BHH * SS, 256>>>(gammas);
    pv_kernel<<<dim3(16, 16), 256>>>();
    out_proj_kernel<<<dim3(4, 32), 256>>>(Wo, bo, out);
}

// round 3
// speedup vs baseline: 2.1104x; 1.1318x over previous
#include <cuda_runtime.h>
#include <math.h>
#include <stdint.h>

#define BB   2
#define SS   2048
#define DD   512
#define HH   8
#define DKK  64
#define BHH  (BB*HH)

// ---------------- scratch (device globals; no allocation allowed) ----------
__device__ float g_qh[BHH*SS*DKK];          // [bh][s][dk]  tf32-rounded bits
__device__ float g_kh[BHH*SS*DKK];          // tf32-rounded bits
__device__ float g_vt[BHH*DKK*SS];          // V^T [bh][dk][s], tf32-rounded bits
__device__ float g_at[BB*SS*DD];            // attention out [b][s][h*64+dk]
__device__ float g_cos[SS*DKK];
__device__ float g_sin[SS*DKK];
__device__ float g_sc[67108864];            // scores/probs [bh][i][j] 256 MiB

// ---------------- helpers ----------------------------------------------------
__device__ __forceinline__ uint32_t f2tf(float f)
{
    uint32_t u;
    asm("cvt.rna.tf32.f32 %0, %1;" : "=r"(u) : "f"(f));
    return u;
}

__device__ __forceinline__ void mma8(float* c, const uint32_t* a, const uint32_t* b)
{
    asm volatile(
        "mma.sync.aligned.m16n8k8.row.col.f32.tf32.tf32.f32 "
        "{%0,%1,%2,%3}, {%4,%5,%6,%7}, {%8,%9}, {%0,%1,%2,%3};\n"
        : "+f"(c[0]), "+f"(c[1]), "+f"(c[2]), "+f"(c[3])
        : "r"(a[0]), "r"(a[1]), "r"(a[2]), "r"(a[3]), "r"(b[0]), "r"(b[1]));
}

// ---------------- RoPE table ------------------------------------------------
__global__ void rope_tab_kernel()
{
    int idx = blockIdx.x * blockDim.x + threadIdx.x;
    if (idx >= SS * 32) return;
    int s = idx >> 5;
    int m = idx & 31;
    float f = (float)s * powf(10000.f, -(float)(2 * m) / 64.f);
    float sn, cs;
    sincosf(f, &sn, &cs);
    g_cos[s*64 + 2*m]     = cs;
    g_cos[s*64 + 2*m + 1] = cs;
    g_sin[s*64 + 2*m]     = sn;
    g_sin[s*64 + 2*m + 1] = sn;
}

// ---------------- fused QKV projection + RoPE (tf32 mma, reg-prefetch) -------
__global__ __launch_bounds__(256) void proj_kernel(
    const float* __restrict__ qx, const float* __restrict__ kx, const float* __restrict__ vx,
    const float* __restrict__ Wq, const float* __restrict__ bq,
    const float* __restrict__ Wk, const float* __restrict__ bk,
    const float* __restrict__ Wv, const float* __restrict__ bv)
{
    __shared__ uint32_t As[128][36];
    __shared__ uint32_t Bs[128][36];

    int which = blockIdx.z;
    const float* X    = (which == 0) ? qx : (which == 1) ? kx : vx;
    const float* W    = (which == 0) ? Wq : (which == 1) ? Wk : Wv;
    const float* bias = (which == 0) ? bq : (which == 1) ? bk : bv;

    int tid  = threadIdx.x;
    int wid  = tid >> 5, lane = tid & 31;
    int g    = lane >> 2, t = lane & 3;
    int wm   = wid >> 2, wn = wid & 3;
    int n0   = blockIdx.x * 128;
    int m0   = blockIdx.y * 128;

    float c[4][4][4];
    #pragma unroll
    for (int mf = 0; mf < 4; mf++)
        #pragma unroll
        for (int nf = 0; nf < 4; nf++)
            #pragma unroll
            for (int u = 0; u < 4; u++) c[mf][nf][u] = 0.f;

    int lr = tid >> 1;
    int lc = (tid & 1) * 16;

    float4 xa[4], wb[4];
    #pragma unroll
    for (int u = 0; u < 4; u++) {
        xa[u] = *(const float4*)(X + (size_t)(m0 + lr) * 512 + lc + u*4);
        wb[u] = *(const float4*)(W + (size_t)(n0 + lr) * 512 + lc + u*4);
    }
    #pragma unroll
    for (int u = 0; u < 4; u++) {
        As[lr][lc+u*4+0] = f2tf(xa[u].x); As[lr][lc+u*4+1] = f2tf(xa[u].y);
        As[lr][lc+u*4+2] = f2tf(xa[u].z); As[lr][lc+u*4+3] = f2tf(xa[u].w);
        Bs[lr][lc+u*4+0] = f2tf(wb[u].x); Bs[lr][lc+u*4+1] = f2tf(wb[u].y);
        Bs[lr][lc+u*4+2] = f2tf(wb[u].z); Bs[lr][lc+u*4+3] = f2tf(wb[u].w);
    }
    __syncthreads();

    for (int k0 = 0; k0 < 512; k0 += 32) {
        int kn = k0 + 32;
        if (kn < 512) {
            #pragma unroll
            for (int u = 0; u < 4; u++) {
                xa[u] = *(const float4*)(X + (size_t)(m0 + lr) * 512 + kn + lc + u*4);
                wb[u] = *(const float4*)(W + (size_t)(n0 + lr) * 512 + kn + lc + u*4);
            }
        }
        #pragma unroll
        for (int k8 = 0; k8 < 32; k8 += 8) {
            uint32_t a[4][4], b[4][2];
            #pragma unroll
            for (int mf = 0; mf < 4; mf++) {
                int r = wm*64 + mf*16 + g;
                a[mf][0] = As[r][k8+t];     a[mf][1] = As[r+8][k8+t];
                a[mf][2] = As[r][k8+t+4];   a[mf][3] = As[r+8][k8+t+4];
            }
            #pragma unroll
            for (int nf = 0; nf < 4; nf++) {
                int rn = wn*32 + nf*8 + g;
                b[nf][0] = Bs[rn][k8+t];    b[nf][1] = Bs[rn][k8+t+4];
            }
            #pragma unroll
            for (int mf = 0; mf < 4; mf++)
                #pragma unroll
                for (int nf = 0; nf < 4; nf++)
                    mma8(c[mf][nf], a[mf], b[nf]);
        }
        __syncthreads();
        if (kn < 512) {
            #pragma unroll
            for (int u = 0; u < 4; u++) {
                As[lr][lc+u*4+0] = f2tf(xa[u].x); As[lr][lc+u*4+1] = f2tf(xa[u].y);
                As[lr][lc+u*4+2] = f2tf(xa[u].z); As[lr][lc+u*4+3] = f2tf(xa[u].w);
                Bs[lr][lc+u*4+0] = f2tf(wb[u].x); Bs[lr][lc+u*4+1] = f2tf(wb[u].y);
                Bs[lr][lc+u*4+2] = f2tf(wb[u].z); Bs[lr][lc+u*4+3] = f2tf(wb[u].w);
            }
            __syncthreads();
        }
    }

    // ---- epilogue: bias (+ RoPE for q/k); store tf32-rounded bits ----
    #pragma unroll
    for (int nf = 0; nf < 4; nf++) {
        int col = n0 + wn*32 + nf*8 + t*2;
        int hh  = col >> 6, dk = col & 63;
        float bce = bias[col], bco = bias[col+1];
        #pragma unroll
        for (int mf = 0; mf < 4; mf++) {
            #pragma unroll
            for (int half = 0; half < 2; half++) {
                int row  = m0 + wm*64 + mf*16 + g + half*8;
                int srow = row & (SS-1);
                int bidx = row >> 11;
                float e = c[mf][nf][half*2+0] + bce;
                float o = c[mf][nf][half*2+1] + bco;
                if (which < 2) {
                    float cs = g_cos[srow*64 + dk];
                    float sn = g_sin[srow*64 + dk];
                    float ne = __uint_as_float(f2tf(e*cs - o*sn));
                    float no = __uint_as_float(f2tf(o*cs + e*sn));
                    float* Y = (which == 0) ? g_qh : g_kh;
                    *(float2*)(Y + (((size_t)(bidx*HH + hh))*SS + srow)*DKK + dk)
                        = make_float2(ne, no);
                } else {
                    size_t vb = (size_t)(bidx*HH + hh) * DKK;
                    g_vt[(vb + dk    )*SS + srow] = __uint_as_float(f2tf(e));
                    g_vt[(vb + dk + 1)*SS + srow] = __uint_as_float(f2tf(o));
                }
            }
        }
    }
}

// ---------------- output projection (tf32 mma, reg-prefetch) -----------------
__global__ __launch_bounds__(256) void out_proj_kernel(
    const float* __restrict__ W, const float* __restrict__ bias, float* __restrict__ out)
{
    __shared__ uint32_t As[128][36];
    __shared__ uint32_t Bs[128][36];

    int tid  = threadIdx.x;
    int wid  = tid >> 5, lane = tid & 31;
    int g    = lane >> 2, t = lane & 3;
    int wm   = wid >> 2, wn = wid & 3;
    int n0   = blockIdx.x * 128;
    int m0   = blockIdx.y * 128;

    float c[4][4][4];
    #pragma unroll
    for (int mf = 0; mf < 4; mf++)
        #pragma unroll
        for (int nf = 0; nf < 4; nf++)
            #pragma unroll
            for (int u = 0; u < 4; u++) c[mf][nf][u] = 0.f;

    int lr = tid >> 1;
    int lc = (tid & 1) * 16;

    float4 xa[4], wb[4];
    #pragma unroll
    for (int u = 0; u < 4; u++) {
        xa[u] = *(const float4*)(g_at + (size_t)(m0 + lr) * 512 + lc + u*4);
        wb[u] = *(const float4*)(W    + (size_t)(n0 + lr) * 512 + lc + u*4);
    }
    #pragma unroll
    for (int u = 0; u < 4; u++) {
        As[lr][lc+u*4+0] = f2tf(xa[u].x); As[lr][lc+u*4+1] = f2tf(xa[u].y);
        As[lr][lc+u*4+2] = f2tf(xa[u].z); As[lr][lc+u*4+3] = f2tf(xa[u].w);
        Bs[lr][lc+u*4+0] = f2tf(wb[u].x); Bs[lr][lc+u*4+1] = f2tf(wb[u].y);
        Bs[lr][lc+u*4+2] = f2tf(wb[u].z); Bs[lr][lc+u*4+3] = f2tf(wb[u].w);
    }
    __syncthreads();

    for (int k0 = 0; k0 < 512; k0 += 32) {
        int kn = k0 + 32;
        if (kn < 512) {
            #pragma unroll
            for (int u = 0; u < 4; u++) {
                xa[u] = *(const float4*)(g_at + (size_t)(m0 + lr) * 512 + kn + lc + u*4);
                wb[u] = *(const float4*)(W    + (size_t)(n0 + lr) * 512 + kn + lc + u*4);
            }
        }
        #pragma unroll
        for (int k8 = 0; k8 < 32; k8 += 8) {
            uint32_t a[4][4], b[4][2];
            #pragma unroll
            for (int mf = 0; mf < 4; mf++) {
                int r = wm*64 + mf*16 + g;
                a[mf][0] = As[r][k8+t];     a[mf][1] = As[r+8][k8+t];
                a[mf][2] = As[r][k8+t+4];   a[mf][3] = As[r+8][k8+t+4];
            }
            #pragma unroll
            for (int nf = 0; nf < 4; nf++) {
                int rn = wn*32 + nf*8 + g;
                b[nf][0] = Bs[rn][k8+t];    b[nf][1] = Bs[rn][k8+t+4];
            }
            #pragma unroll
            for (int mf = 0; mf < 4; mf++)
                #pragma unroll
                for (int nf = 0; nf < 4; nf++)
                    mma8(c[mf][nf], a[mf], b[nf]);
        }
        __syncthreads();
        if (kn < 512) {
            #pragma unroll
            for (int u = 0; u < 4; u++) {
                As[lr][lc+u*4+0] = f2tf(xa[u].x); As[lr][lc+u*4+1] = f2tf(xa[u].y);
                As[lr][lc+u*4+2] = f2tf(xa[u].z); As[lr][lc+u*4+3] = f2tf(xa[u].w);
                Bs[lr][lc+u*4+0] = f2tf(wb[u].x); Bs[lr][lc+u*4+1] = f2tf(wb[u].y);
                Bs[lr][lc+u*4+2] = f2tf(wb[u].z); Bs[lr][lc+u*4+3] = f2tf(wb[u].w);
            }
            __syncthreads();
        }
    }

    #pragma unroll
    for (int nf = 0; nf < 4; nf++) {
        int col = n0 + wn*32 + nf*8 + t*2;
        float bce = bias[col], bco = bias[col+1];
        #pragma unroll
        for (int mf = 0; mf < 4; mf++) {
            #pragma unroll
            for (int half = 0; half < 2; half++) {
                int row = m0 + wm*64 + mf*16 + g + half*8;
                *(float2*)(out + (size_t)row*512 + col)
                    = make_float2(c[mf][nf][half*2+0] + bce, c[mf][nf][half*2+1] + bco);
            }
        }
    }
}

// ---------------- causal score GEMM S = (Q K^T)/8 (raw tf32 bits) ------------
__global__ __launch_bounds__(256) void score_kernel()
{
    int qt = blockIdx.x, kt = blockIdx.y, bh = blockIdx.z;
    if (kt > qt) return;

    __shared__ uint32_t Qs[128][36];
    __shared__ uint32_t Ks[128][36];

    const uint32_t* qb = (const uint32_t*)g_qh + (size_t)bh * SS * DKK;
    const uint32_t* kb = (const uint32_t*)g_kh + (size_t)bh * SS * DKK;

    int tid  = threadIdx.x;
    int wid  = tid >> 5, lane = tid & 31;
    int g    = lane >> 2, t = lane & 3;
    int wm   = wid >> 2, wn = wid & 3;
    int i0   = qt * 128, j0 = kt * 128;

    float c[4][4][4];
    #pragma unroll
    for (int mf = 0; mf < 4; mf++)
        #pragma unroll
        for (int nf = 0; nf < 4; nf++)
            #pragma unroll
            for (int u = 0; u < 4; u++) c[mf][nf][u] = 0.f;

    int lr = tid >> 1;
    int lc = (tid & 1) * 16;

    uint4 qv[4], kv[4];
    #pragma unroll
    for (int u = 0; u < 4; u++) {
        qv[u] = *(const uint4*)(qb + (size_t)(i0 + lr) * 64 + lc + u*4);
        kv[u] = *(const uint4*)(kb + (size_t)(j0 + lr) * 64 + lc + u*4);
    }
    #pragma unroll
    for (int u = 0; u < 4; u++) {
        *(uint4*)&Qs[lr][lc+u*4] = qv[u];
        *(uint4*)&Ks[lr][lc+u*4] = kv[u];
    }
    __syncthreads();

    #pragma unroll
    for (int k0 = 0; k0 < 64; k0 += 32) {
        int kn = k0 + 32;
        if (kn < 64) {
            #pragma unroll
            for (int u = 0; u < 4; u++) {
                qv[u] = *(const uint4*)(qb + (size_t)(i0 + lr) * 64 + kn + lc + u*4);
                kv[u] = *(const uint4*)(kb + (size_t)(j0 + lr) * 64 + kn + lc + u*4);
            }
        }
        #pragma unroll
        for (int k8 = 0; k8 < 32; k8 += 8) {
            uint32_t a[4][4], b[4][2];
            #pragma unroll
            for (int mf = 0; mf < 4; mf++) {
                int r = wm*64 + mf*16 + g;
                a[mf][0] = Qs[r][k8+t];     a[mf][1] = Qs[r+8][k8+t];
                a[mf][2] = Qs[r][k8+t+4];   a[mf][3] = Qs[r+8][k8+t+4];
            }
            #pragma unroll
            for (int nf = 0; nf < 4; nf++) {
                int rn = wn*32 + nf*8 + g;
                b[nf][0] = Ks[rn][k8+t];    b[nf][1] = Ks[rn][k8+t+4];
            }
            #pragma unroll
            for (int mf = 0; mf < 4; mf++)
                #pragma unroll
                for (int nf = 0; nf < 4; nf++)
                    mma8(c[mf][nf], a[mf], b[nf]);
        }
        __syncthreads();
        if (kn < 64) {
            #pragma unroll
            for (int u = 0; u < 4; u++) {
                *(uint4*)&Qs[lr][lc+u*4] = qv[u];
                *(uint4*)&Ks[lr][lc+u*4] = kv[u];
            }
            __syncthreads();
        }
    }

    float* C = g_sc + (size_t)bh * SS * SS;
    #pragma unroll
    for (int nf = 0; nf < 4; nf++) {
        int col = j0 + wn*32 + nf*8 + t*2;
        #pragma unroll
        for (int mf = 0; mf < 4; mf++) {
            #pragma unroll
            for (int half = 0; half < 2; half++) {
                int row = i0 + wm*64 + mf*16 + g + half*8;
                *(float2*)(C + (size_t)row*SS + col)
                    = make_float2(c[mf][nf][half*2+0] * 0.125f,
                                  c[mf][nf][half*2+1] * 0.125f);
            }
        }
    }
}

// ---------------- per-row decay + double softmax (lean version) --------------
__global__ __launch_bounds__(256) void row_kernel(const float* __restrict__ gammas)
{
    __shared__ float swp[34];
    int rid = blockIdx.x;
    int bh  = rid >> 11;
    int i   = rid & (SS - 1);
    int h   = bh & (HH - 1);
    int tid = threadIdx.x, wid = tid >> 5, lane = tid & 31;

    float* row = g_sc + (size_t)bh * SS * SS + (size_t)i * SS;
    int lim = ((i >> 7) + 1) << 7;

    if (i == 0) {
        if (tid < 32) ((float4*)row)[tid] = make_float4(0.f, 0.f, 0.f, 0.f);
        return;
    }

    const bool act = (wid << 8) < lim;      // warp covers [wid*256, wid*256+256)
    const int base = tid * 8;

    float sv[8];
    float mloc = -3.0e38f;
    if (act) {
        float4 v0 = *(const float4*)(row + base);
        float4 v1 = *(const float4*)(row + base + 4);
        float tmp[8] = {v0.x, v0.y, v0.z, v0.w, v1.x, v1.y, v1.z, v1.w};
        #pragma unroll
        for (int u = 0; u < 8; u++) {
            sv[u] = (base + u <= i) ? tmp[u] : -3.0e38f;
            mloc  = fmaxf(mloc, sv[u]);
        }
    }

    // --- softmax 1: block max ---
    #pragma unroll
    for (int o = 16; o > 0; o >>= 1)
        mloc = fmaxf(mloc, __shfl_xor_sync(0xffffffffu, mloc, o));
    if (lane == 0) swp[wid] = mloc;
    __syncthreads();
    if (tid == 0) {
        float m = swp[0];
        #pragma unroll
        for (int w = 1; w < 8; w++) m = fmaxf(m, swp[w]);
        swp[8] = m;
    }
    __syncthreads();
    float m1 = swp[8];

    // --- exp + thread-local inclusive prefix (masked lanes give exactly 0) ---
    float epre[8];
    float run = 0.f;
    if (act) {
        #pragma unroll
        for (int u = 0; u < 8; u++) {
            run += __expf(sv[u] - m1);
            epre[u] = run;
        }
    }

    // --- warp inclusive scan + cross-warp combine ---
    float x = run;
    #pragma unroll
    for (int d = 1; d < 32; d <<= 1) {
        float y = __shfl_up_sync(0xffffffffu, x, d);
        if (lane >= d) x += y;
    }
    if (lane == 31) swp[16 + wid] = x;
    __syncthreads();
    if (tid == 0) {
        float s = 0.f;
        #pragma unroll
        for (int w = 0; w < 8; w++) { float tw = swp[16 + w]; swp[24 + w] = s; s += tw; }
        swp[32] = s;
    }
    __syncthreads();
    float l1 = swp[32];

    // --- decay + rescoring + softmax2 numerator (m2 = max(m1,0) bound) ---
    float e2[8];
    float lsum = 0.f;
    if (act) {
        float off = swp[24 + wid] + (x - run);
        float gam = gammas[h * SS + i];
        float sp  = (gam > 20.f) ? gam : log1pf(__expf(gam));
        float gg  = -sp;
        float inv_l1 = 1.f / l1;
        float fi  = (float)i - (float)base;
        float m2  = fmaxf(m1, 0.f);
        #pragma unroll
        for (int u = 0; u < 8; u++) {
            float suffix = l1 - (off + epre[u]);
            float dsq    = suffix * inv_l1 * (fi - (float)u);
            float dist   = sqrtf(fmaxf(dsq, 0.f));
            float eff    = fmaxf(__expf(dist * gg), 1e-5f);
            float tv     = eff * sv[u];
            e2[u] = __expf(tv - m2);
            lsum += e2[u];
        }
    }

    // --- softmax 2: block sum ---
    #pragma unroll
    for (int o = 16; o > 0; o >>= 1)
        lsum += __shfl_xor_sync(0xffffffffu, lsum, o);
    if (lane == 0) swp[wid] = lsum;
    __syncthreads();
    if (tid == 0) {
        float s = 0.f;
        #pragma unroll
        for (int w = 0; w < 8; w++) s += swp[w];
        swp[9] = s;
    }
    __syncthreads();

    if (act && base < lim) {
        float inv = 1.f / swp[9];
        *(float4*)(row + base)     = make_float4(e2[0]*inv, e2[1]*inv, e2[2]*inv, e2[3]*inv);
        *(float4*)(row + base + 4) = make_float4(e2[4]*inv, e2[5]*inv, e2[6]*inv, e2[7]*inv);
    }
}

// ---------------- causal PV GEMM O = P @ V (tf32 mma, reg-prefetch) ----------
__global__ __launch_bounds__(256) void pv_kernel()
{
    int qt = blockIdx.x, bh = blockIdx.y;

    __shared__ uint32_t Ps[128][36];
    __shared__ uint32_t Vs[64][36];

    const float*    P  = g_sc + (size_t)bh * SS * SS;
    const uint32_t* vb = (const uint32_t*)g_vt + (size_t)bh * DKK * SS;

    int tid  = threadIdx.x;
    int wid  = tid >> 5, lane = tid & 31;
    int g    = lane >> 2, t = lane & 3;
    int wm   = wid >> 1, wn = wid & 1;
    int m0   = qt * 128;

    float c[2][4][4];
    #pragma unroll
    for (int mf = 0; mf < 2; mf++)
        #pragma unroll
        for (int nf = 0; nf < 4; nf++)
            #pragma unroll
            for (int u = 0; u < 4; u++) c[mf][nf][u] = 0.f;

    int lr = tid >> 1;
    int lc = (tid & 1) * 16;
    int vrow0 = tid >> 3, vc0 = (tid & 7) * 4;          // Vs fill slot 0
    int vrow1 = (tid + 256) >> 3, vc1 = vc0;            // Vs fill slot 1
    int kmax = (qt + 1) * 128;

    float4 pv[4];
    uint4  vv[2];
    #pragma unroll
    for (int u = 0; u < 4; u++)
        pv[u] = *(const float4*)(P + (size_t)(m0 + lr) * SS + lc + u*4);
    vv[0] = *(const uint4*)(vb + (size_t)vrow0 * SS + vc0);
    vv[1] = *(const uint4*)(vb + (size_t)vrow1 * SS + vc1);

    #pragma unroll
    for (int u = 0; u < 4; u++) {
        Ps[lr][lc+u*4+0] = f2tf(pv[u].x); Ps[lr][lc+u*4+1] = f2tf(pv[u].y);
        Ps[lr][lc+u*4+2] = f2tf(pv[u].z); Ps[lr][lc+u*4+3] = f2tf(pv[u].w);
    }
    *(uint4*)&Vs[vrow0][vc0] = vv[0];
    *(uint4*)&Vs[vrow1][vc1] = vv[1];
    __syncthreads();

    for (int k0 = 0; k0 < kmax; k0 += 32) {
        int kn = k0 + 32;
        if (kn < kmax) {
            #pragma unroll
            for (int u = 0; u < 4; u++)
                pv[u] = *(const float4*)(P + (size_t)(m0 + lr) * SS + kn + lc + u*4);
            vv[0] = *(const uint4*)(vb + (size_t)vrow0 * SS + kn + vc0);
            vv[1] = *(const uint4*)(vb + (size_t)vrow1 * SS + kn + vc1);
        }
        #pragma unroll
        for (int k8 = 0; k8 < 32; k8 += 8) {
            uint32_t a[2][4], b[4][2];
            #pragma unroll
            for (int mf = 0; mf < 2; mf++) {
                int r = wm*32 + mf*16 + g;
                a[mf][0] = Ps[r][k8+t];     a[mf][1] = Ps[r+8][k8+t];
                a[mf][2] = Ps[r][k8+t+4];   a[mf][3] = Ps[r+8][k8+t+4];
            }
            #pragma unroll
            for (int nf = 0; nf < 4; nf++) {
                int rn = wn*32 + nf*8 + g;
                b[nf][0] = Vs[rn][k8+t];    b[nf][1] = Vs[rn][k8+t+4];
            }
            #pragma unroll
            for (int mf = 0; mf < 2; mf++)
                #pragma unroll
                for (int nf = 0; nf < 4; nf++)
                    mma8(c[mf][nf], a[mf], b[nf]);
        }
        __syncthreads();
        if (kn < kmax) {
            #pragma unroll
            for (int u = 0; u < 4; u++) {
                Ps[lr][lc+u*4+0] = f2tf(pv[u].x); Ps[lr][lc+u*4+1] = f2tf(pv[u].y);
                Ps[lr][lc+u*4+2] = f2tf(pv[u].z); Ps[lr][lc+u*4+3] = f2tf(pv[u].w);
            }
            *(uint4*)&Vs[vrow0][vc0] = vv[0];
            *(uint4*)&Vs[vrow1][vc1] = vv[1];
            __syncthreads();
        }
    }

    int b = bh >> 3, h = bh & 7;
    #pragma unroll
    for (int nf = 0; nf < 4; nf++) {
        int dk = wn*32 + nf*8 + t*2;
        #pragma unroll
        for (int mf = 0; mf < 2; mf++) {
            #pragma unroll
            for (int half = 0; half < 2; half++) {
                int s = m0 + wm*32 + mf*16 + g + half*8;
                *(float2*)(g_at + ((size_t)b * SS + s) * DD + h*64 + dk)
                    = make_float2(c[mf][nf][half*2+0], c[mf][nf][half*2+1]);
            }
        }
    }
}

// ---------------- launcher ----------------------------------------------------
extern "C" void kernel_launch(void* const* d_in, const int* in_sizes, int n_in,
                              void* d_out, int out_size)
{
    const float* q      = (const float*)d_in[0];
    const float* k      = (const float*)d_in[1];
    const float* v      = (const float*)d_in[2];
    const float* Wq     = (const float*)d_in[5];
    const float* bq     = (const float*)d_in[6];
    const float* Wk     = (const float*)d_in[7];
    const float* bk     = (const float*)d_in[8];
    const float* Wv     = (const float*)d_in[9];
    const float* bv     = (const float*)d_in[10];
    const float* Wo     = (const float*)d_in[11];
    const float* bo     = (const float*)d_in[12];
    const float* gammas = (const float*)d_in[13];
    float* out = (float*)d_out;

    rope_tab_kernel<<<(SS * 32 + 255) / 256, 256>>>();
    proj_kernel<<<dim3(4, 32, 3), 256>>>(q, k, v, Wq, bq, Wk, bk, Wv, bv);
    score_kernel<<<dim3(16, 16, 16), 256>>>();
    row_kernel<<<BHH * SS, 256>>>(gammas);
    pv_kernel<<<dim3(16, 16), 256>>>();
    out_proj_kernel<<<dim3(4, 32), 256>>>(Wo, bo, out);
}